// round 13
// baseline (speedup 1.0000x reference)
#include <cuda_runtime.h>
#include <cuda_bf16.h>
#include <math.h>

#define NN 50000
#define EE 800000
#define DD 128
#define MAXN 4
#define SLOT_INF 0xFFFFFFFFu
#define NBLOCKS 444            // 148 SMs x 3 resident blocks (co-resident by construction)
#define NPB 113                // ceil(50000/444) nodes per block
#define NIT 15                 // ceil(113/8) iterations per sub-lane
#define EDGE_BLOCKS ((EE / 4 + 255) / 256)

// ---------------- scratch (device globals; no allocation allowed) ----------
__device__ unsigned g_slots[NN * MAXN];    // 4 smallest in-edge ids per node
__device__ float    g_blankp[2][DD];
__device__ float    g_sum[2][DD];
__device__ float    g_sq[2][DD];
__device__ int      g_done[2];

// ---------------- kernels ---------------------------------------------------

__device__ __forceinline__ void slot_insert(unsigned* sl, unsigned v) {
#pragma unroll
    for (int k = 0; k < MAXN; k++) {
        unsigned old = atomicMin(&sl[k], v);
        if (old == SLOT_INF) break;   // inserted into empty slot
        v = max(v, old);              // displaced (larger) value cascades
    }
}

// Edge pass: the 4 prune loads of a thread's int4 of edges are independent,
// so they are issued together (MLP=4) BEFORE any cascade — collapsing the
// per-thread critical path from 4x(load+cascade) to ~1 load + cascades.
// Prune reads are plain (L1-cacheable) and stale-HIGH only => skip is safe.
// One extra block computes blank_p for both layers + zeroes stats/barriers.
__global__ void edge_pass_kernel(const int4* __restrict__ dst4,
                                 const float* __restrict__ W0, const float* __restrict__ b0,
                                 const float* __restrict__ blank0,
                                 const float* __restrict__ W1, const float* __restrict__ b1,
                                 const float* __restrict__ blank1)
{
    if ((int)blockIdx.x < EDGE_BLOCKS) {
        int t = blockIdx.x * blockDim.x + threadIdx.x;
        if (t >= EE / 4) return;
        int4 d = __ldg(&dst4[t]);
        unsigned e0 = (unsigned)(t * 4);

        unsigned* sl0 = &g_slots[d.x * MAXN];
        unsigned* sl1 = &g_slots[d.y * MAXN];
        unsigned* sl2 = &g_slots[d.z * MAXN];
        unsigned* sl3 = &g_slots[d.w * MAXN];

        // 4 independent prune loads issued together
        unsigned t0 = sl0[MAXN - 1];
        unsigned t1 = sl1[MAXN - 1];
        unsigned t2 = sl2[MAXN - 1];
        unsigned t3 = sl3[MAXN - 1];

        if (e0 + 0 < t0) slot_insert(sl0, e0 + 0);
        if (e0 + 1 < t1) slot_insert(sl1, e0 + 1);
        if (e0 + 2 < t2) slot_insert(sl2, e0 + 2);
        if (e0 + 3 < t3) slot_insert(sl3, e0 + 3);
    } else {
        // blankp for both layers + zero stats + barrier counters
        int t = threadIdx.x;           // 0..255
        int layer = t >> 7;            // 0 or 1
        int d = t & 127;
        const float* W  = layer ? W1 : W0;
        const float* b  = layer ? b1 : b0;
        const float* bl = layer ? blank1 : blank0;
        float s = b[d];
#pragma unroll 8
        for (int j = 0; j < DD; j++) s += W[d * DD + j] * bl[j];
        g_blankp[layer][d] = s;
        g_sum[layer][d] = 0.0f;
        g_sq[layer][d]  = 0.0f;
        if (t == 0) { g_done[0] = 0; g_done[1] = 0; }
    }
}

// Fused persistent conv + batchnorm-apply, software-pipelined phase 1.
// Phase 0 converts this block's slot records (edge ids) into source-node ids
// directly in smem — no global srcn array, no prep kernel.
__global__ __launch_bounds__(256, 3) void fused_kernel(
    const float4* __restrict__ x4, const int* __restrict__ src,
    const float* __restrict__ cw, const float* __restrict__ cb,
    const float* __restrict__ a_p,
    const float* __restrict__ gamma, const float* __restrict__ beta,
    float4* __restrict__ out4, int layer)
{
    extern __shared__ float4 sh[];          // [NPB][32] h rows
    __shared__ int4   s_srcn[NPB];
    __shared__ float4 ssum[256];
    __shared__ float4 ssq[256];
    __shared__ float  smu[DD];
    __shared__ float  sscale[DD];

    int dg  = threadIdx.x & 31;    // dim group: dims 4*dg .. 4*dg+3
    int sub = threadIdx.x >> 5;    // 0..7 node sub-lanes
    float c0 = __ldg(cw + 0), c1 = __ldg(cw + 1), c2 = __ldg(cw + 2), c3 = __ldg(cw + 3);
    float cbv = __ldg(cb);
    float av  = __ldg(a_p);
    float4 bp = *reinterpret_cast<const float4*>(&g_blankp[layer][dg * 4]);

    int blockStart = blockIdx.x * NPB;

    // ---- phase 0: slots -> srcn window, straight into smem ----
    for (int k = threadIdx.x; k < NPB; k += 256) {
        int i = blockStart + k;
        int4 r = make_int4(-1, -1, -1, -1);
        if (i < NN) {
            uint4 s = *reinterpret_cast<const uint4*>(&g_slots[i * 4]);
            r.x = (s.x == SLOT_INF) ? -1 : __ldg(&src[s.x]);
            r.y = (s.y == SLOT_INF) ? -1 : __ldg(&src[s.y]);
            r.z = (s.z == SLOT_INF) ? -1 : __ldg(&src[s.z]);
            r.w = (s.w == SLOT_INF) ? -1 : __ldg(&src[s.w]);
        }
        s_srcn[k] = r;
    }
    __syncthreads();

    float4 lsum = make_float4(0.f, 0.f, 0.f, 0.f);
    float4 lsq  = make_float4(0.f, 0.f, 0.f, 0.f);

    // ---- phase 1: conv into smem, 2-stage software pipeline ----
    float4 pv0, pv1, pv2, pv3, pxv;
    int pvalid, ploc;
    {
        int local = sub;                       // it = 0; sub < 8 <= NPB
        ploc   = local;
        pvalid = (blockStart + local < NN);
        int i = blockStart + local; if (i >= NN) i = NN - 1;
        int4 s = s_srcn[local];
        pv0 = (s.x < 0) ? bp : __ldg(&x4[(size_t)s.x * 32 + dg]);
        pv1 = (s.y < 0) ? bp : __ldg(&x4[(size_t)s.y * 32 + dg]);
        pv2 = (s.z < 0) ? bp : __ldg(&x4[(size_t)s.z * 32 + dg]);
        pv3 = (s.w < 0) ? bp : __ldg(&x4[(size_t)s.w * 32 + dg]);
        pxv = __ldg(&x4[(size_t)i * 32 + dg]);
    }

#pragma unroll
    for (int it = 0; it < NIT; it++) {
        float4 nv0, nv1, nv2, nv3, nxv;
        int nvalid = 0, nloc = 0;
        if (it + 1 < NIT) {                    // compile-time after unroll
            int local = (it + 1) * 8 + sub;
            nloc   = local;
            nvalid = (local < NPB) && (blockStart + local < NN);
            int li = (local < NPB) ? local : NPB - 1;
            int i = blockStart + li; if (i >= NN) i = NN - 1;
            int4 s = s_srcn[li];
            nv0 = (s.x < 0) ? bp : __ldg(&x4[(size_t)s.x * 32 + dg]);
            nv1 = (s.y < 0) ? bp : __ldg(&x4[(size_t)s.y * 32 + dg]);
            nv2 = (s.z < 0) ? bp : __ldg(&x4[(size_t)s.z * 32 + dg]);
            nv3 = (s.w < 0) ? bp : __ldg(&x4[(size_t)s.w * 32 + dg]);
            nxv = __ldg(&x4[(size_t)i * 32 + dg]);
        }

        if (pvalid) {
            float4 v0 = pv0, v1 = pv1, v2 = pv2, v3 = pv3;
            float t;
#define CSWAP(A,B) \
            t = fminf(A.x,B.x); B.x = fmaxf(A.x,B.x); A.x = t; \
            t = fminf(A.y,B.y); B.y = fmaxf(A.y,B.y); A.y = t; \
            t = fminf(A.z,B.z); B.z = fmaxf(A.z,B.z); A.z = t; \
            t = fminf(A.w,B.w); B.w = fmaxf(A.w,B.w); A.w = t;
            CSWAP(v0, v1)
            CSWAP(v2, v3)
            CSWAP(v0, v2)
            CSWAP(v1, v3)
            CSWAP(v1, v2)
#undef CSWAP
            float4 hv;
            hv.x = av * pxv.x + v0.x * c0 + v1.x * c1 + v2.x * c2 + v3.x * c3 + cbv;
            hv.y = av * pxv.y + v0.y * c0 + v1.y * c1 + v2.y * c2 + v3.y * c3 + cbv;
            hv.z = av * pxv.z + v0.z * c0 + v1.z * c1 + v2.z * c2 + v3.z * c3 + cbv;
            hv.w = av * pxv.w + v0.w * c0 + v1.w * c1 + v2.w * c2 + v3.w * c3 + cbv;
            sh[ploc * 32 + dg] = hv;
            lsum.x += hv.x; lsum.y += hv.y; lsum.z += hv.z; lsum.w += hv.w;
            lsq.x += hv.x * hv.x; lsq.y += hv.y * hv.y;
            lsq.z += hv.z * hv.z; lsq.w += hv.w * hv.w;
        }

        pv0 = nv0; pv1 = nv1; pv2 = nv2; pv3 = nv3; pxv = nxv;
        pvalid = nvalid; ploc = nloc;
    }

    // ---- block reduce + global partials ----
    ssum[threadIdx.x] = lsum;
    ssq[threadIdx.x]  = lsq;
    __syncthreads();
    if (threadIdx.x < 32) {
        float4 a = ssum[threadIdx.x];
        float4 q = ssq[threadIdx.x];
#pragma unroll
        for (int k = 1; k < 8; k++) {
            float4 a2 = ssum[threadIdx.x + 32 * k];
            float4 q2 = ssq[threadIdx.x + 32 * k];
            a.x += a2.x; a.y += a2.y; a.z += a2.z; a.w += a2.w;
            q.x += q2.x; q.y += q2.y; q.z += q2.z; q.w += q2.w;
        }
        int d0 = threadIdx.x * 4;
        atomicAdd(&g_sum[layer][d0 + 0], a.x);
        atomicAdd(&g_sum[layer][d0 + 1], a.y);
        atomicAdd(&g_sum[layer][d0 + 2], a.z);
        atomicAdd(&g_sum[layer][d0 + 3], a.w);
        atomicAdd(&g_sq[layer][d0 + 0], q.x);
        atomicAdd(&g_sq[layer][d0 + 1], q.y);
        atomicAdd(&g_sq[layer][d0 + 2], q.z);
        atomicAdd(&g_sq[layer][d0 + 3], q.w);
    }

    // ---- soft grid barrier (all blocks co-resident) ----
    __threadfence();
    if (threadIdx.x == 0) {
        atomicAdd(&g_done[layer], 1);
        volatile int* dp = &g_done[layer];
        while (*dp < NBLOCKS) { __nanosleep(100); }
    }
    __syncthreads();
    __threadfence();

    // ---- phase 2: stats + apply ----
    if (threadIdx.x < DD) {
        int d = threadIdx.x;
        float mu  = __ldcg(&g_sum[layer][d]) * (1.0f / NN);
        float var = __ldcg(&g_sq[layer][d]) * (1.0f / NN) - mu * mu;
        smu[d]    = mu;
        sscale[d] = rsqrtf(var + 1e-5f) * __ldg(&gamma[d]);
    }
    __syncthreads();

    int d0 = dg * 4;
    float m0 = smu[d0], m1 = smu[d0 + 1], m2 = smu[d0 + 2], m3 = smu[d0 + 3];
    float s0 = sscale[d0], s1 = sscale[d0 + 1], s2 = sscale[d0 + 2], s3 = sscale[d0 + 3];
    float e0 = __ldg(&beta[d0]), e1 = __ldg(&beta[d0 + 1]);
    float e2 = __ldg(&beta[d0 + 2]), e3 = __ldg(&beta[d0 + 3]);

#pragma unroll 4
    for (int it = 0; it < NIT; it++) {
        int local = it * 8 + sub;
        int i = blockStart + local;
        if (local < NPB && i < NN) {
            float4 hv = sh[local * 32 + dg];
            float4 xv = __ldg(&x4[(size_t)i * 32 + dg]);
            float4 o;
            o.x = xv.x + (hv.x - m0) * s0 + e0;
            o.y = xv.y + (hv.y - m1) * s1 + e1;
            o.z = xv.z + (hv.z - m2) * s2 + e2;
            o.w = xv.w + (hv.w - m3) * s3 + e3;
            out4[(size_t)i * 32 + dg] = o;
        }
    }
}

// ---------------- launch -----------------------------------------------------

extern "C" void kernel_launch(void* const* d_in, const int* in_sizes, int n_in,
                              void* d_out, int out_size)
{
    const float* x   = (const float*)d_in[0];
    const int*   ei  = (const int*)d_in[1];
    const int*   src = ei;        // edge_index[0]
    const int*   dst = ei + EE;   // edge_index[1]

    const float* W0     = (const float*)d_in[2];
    const float* b0     = (const float*)d_in[3];
    const float* cw0    = (const float*)d_in[4];
    const float* cb0    = (const float*)d_in[5];
    const float* a0     = (const float*)d_in[6];
    const float* g0     = (const float*)d_in[7];
    const float* be0    = (const float*)d_in[8];
    const float* blank0 = (const float*)d_in[9];
    const float* W1     = (const float*)d_in[10];
    const float* b1     = (const float*)d_in[11];
    const float* cw1    = (const float*)d_in[12];
    const float* cb1    = (const float*)d_in[13];
    const float* a1     = (const float*)d_in[14];
    const float* g1     = (const float*)d_in[15];
    const float* be1    = (const float*)d_in[16];
    const float* blank1 = (const float*)d_in[17];

    float* out = (float*)d_out;

    const int smem_bytes = NPB * 32 * sizeof(float4);   // 57,856 B

    static bool attr_set = false;
    if (!attr_set) {
        cudaFuncSetAttribute(fused_kernel,
                             cudaFuncAttributeMaxDynamicSharedMemorySize, smem_bytes);
        attr_set = true;
    }

    // slots init: 0xFF byte pattern == SLOT_INF (unsigned), via async memset
    void* slots_ptr = nullptr;
    cudaGetSymbolAddress(&slots_ptr, g_slots);
    cudaMemsetAsync(slots_ptr, 0xFF, sizeof(unsigned) * NN * MAXN);

    // edge pass + (extra block) blankp/stat-zero
    edge_pass_kernel<<<EDGE_BLOCKS + 1, 256>>>((const int4*)dst,
                                               W0, b0, blank0, W1, b1, blank1);

    // layer 0: reads x, writes x1 into d_out
    fused_kernel<<<NBLOCKS, 256, smem_bytes>>>((const float4*)x, src, cw0, cb0, a0,
                                               g0, be0, (float4*)out, 0);
    // layer 1: reads d_out, writes final into d_out (safe: all gathers precede
    // any write because every write is after the grid barrier)
    fused_kernel<<<NBLOCKS, 256, smem_bytes>>>((const float4*)out, src, cw1, cb1, a1,
                                               g1, be1, (float4*)out, 1);
}

// round 14
// speedup vs baseline: 1.0244x; 1.0244x over previous
#include <cuda_runtime.h>
#include <cuda_bf16.h>
#include <math.h>

#define NN 50000
#define EE 800000
#define DD 128
#define MAXN 4
#define SLOT_INF 0xFFFFFFFFu
#define NBLOCKS 444            // 148 SMs x 3 resident blocks (co-resident by construction)
#define NPB 113                // ceil(50000/444) nodes per block
#define NIT 15                 // ceil(113/8) iterations per sub-lane
#define EDGE_BLOCKS ((EE + 255) / 256)

// ---------------- scratch (device globals; no allocation allowed) ----------
__device__ unsigned g_slots[NN * MAXN];    // 4 smallest in-edge ids per node
__device__ float    g_blankp[2][DD];
__device__ float    g_sum[2][DD];
__device__ float    g_sq[2][DD];
__device__ int      g_done[2];

// ---------------- kernels ---------------------------------------------------

// Edge pass: ONE edge per thread. Per-thread critical path = one prune load +
// (for ~40% of edges) one atomicMin cascade. Parallelism comes from 800k
// threads instead of intra-thread ILP (which memory-ordering rules forbid
// across atomics). Prune read is plain/L1 and stale-HIGH only => skip safe.
// One extra block computes blank_p for both layers + zeroes stats/barriers.
__global__ void edge_pass_kernel(const int* __restrict__ dst,
                                 const float* __restrict__ W0, const float* __restrict__ b0,
                                 const float* __restrict__ blank0,
                                 const float* __restrict__ W1, const float* __restrict__ b1,
                                 const float* __restrict__ blank1)
{
    if ((int)blockIdx.x < EDGE_BLOCKS) {
        int e = blockIdx.x * blockDim.x + threadIdx.x;
        if (e >= EE) return;
        int node = __ldg(&dst[e]);
        unsigned v = (unsigned)e;
        unsigned* sl = &g_slots[node * MAXN];
        if (v >= sl[MAXN - 1]) return;     // plain (L1-cacheable) stale-high read
#pragma unroll
        for (int k = 0; k < MAXN; k++) {
            unsigned old = atomicMin(&sl[k], v);
            if (old == SLOT_INF) break;    // inserted into empty slot
            v = max(v, old);               // displaced (larger) value cascades
        }
    } else {
        // blankp for both layers + zero stats + barrier counters
        int t = threadIdx.x;           // 0..255
        int layer = t >> 7;            // 0 or 1
        int d = t & 127;
        const float* W  = layer ? W1 : W0;
        const float* b  = layer ? b1 : b0;
        const float* bl = layer ? blank1 : blank0;
        float s = b[d];
#pragma unroll 8
        for (int j = 0; j < DD; j++) s += W[d * DD + j] * bl[j];
        g_blankp[layer][d] = s;
        g_sum[layer][d] = 0.0f;
        g_sq[layer][d]  = 0.0f;
        if (t == 0) { g_done[0] = 0; g_done[1] = 0; }
    }
}

// Fused persistent conv + batchnorm-apply, software-pipelined phase 1.
// Phase 0 converts this block's slot records (edge ids) into source-node ids
// directly in smem — no global srcn array, no prep kernel.
__global__ __launch_bounds__(256, 3) void fused_kernel(
    const float4* __restrict__ x4, const int* __restrict__ src,
    const float* __restrict__ cw, const float* __restrict__ cb,
    const float* __restrict__ a_p,
    const float* __restrict__ gamma, const float* __restrict__ beta,
    float4* __restrict__ out4, int layer)
{
    extern __shared__ float4 sh[];          // [NPB][32] h rows
    __shared__ int4   s_srcn[NPB];
    __shared__ float4 ssum[256];
    __shared__ float4 ssq[256];
    __shared__ float  smu[DD];
    __shared__ float  sscale[DD];

    int dg  = threadIdx.x & 31;    // dim group: dims 4*dg .. 4*dg+3
    int sub = threadIdx.x >> 5;    // 0..7 node sub-lanes
    float c0 = __ldg(cw + 0), c1 = __ldg(cw + 1), c2 = __ldg(cw + 2), c3 = __ldg(cw + 3);
    float cbv = __ldg(cb);
    float av  = __ldg(a_p);
    float4 bp = *reinterpret_cast<const float4*>(&g_blankp[layer][dg * 4]);

    int blockStart = blockIdx.x * NPB;

    // ---- phase 0: slots -> srcn window, straight into smem ----
    for (int k = threadIdx.x; k < NPB; k += 256) {
        int i = blockStart + k;
        int4 r = make_int4(-1, -1, -1, -1);
        if (i < NN) {
            uint4 s = *reinterpret_cast<const uint4*>(&g_slots[i * 4]);
            r.x = (s.x == SLOT_INF) ? -1 : __ldg(&src[s.x]);
            r.y = (s.y == SLOT_INF) ? -1 : __ldg(&src[s.y]);
            r.z = (s.z == SLOT_INF) ? -1 : __ldg(&src[s.z]);
            r.w = (s.w == SLOT_INF) ? -1 : __ldg(&src[s.w]);
        }
        s_srcn[k] = r;
    }
    __syncthreads();

    float4 lsum = make_float4(0.f, 0.f, 0.f, 0.f);
    float4 lsq  = make_float4(0.f, 0.f, 0.f, 0.f);

    // ---- phase 1: conv into smem, 2-stage software pipeline ----
    float4 pv0, pv1, pv2, pv3, pxv;
    int pvalid, ploc;
    {
        int local = sub;                       // it = 0; sub < 8 <= NPB
        ploc   = local;
        pvalid = (blockStart + local < NN);
        int i = blockStart + local; if (i >= NN) i = NN - 1;
        int4 s = s_srcn[local];
        pv0 = (s.x < 0) ? bp : __ldg(&x4[(size_t)s.x * 32 + dg]);
        pv1 = (s.y < 0) ? bp : __ldg(&x4[(size_t)s.y * 32 + dg]);
        pv2 = (s.z < 0) ? bp : __ldg(&x4[(size_t)s.z * 32 + dg]);
        pv3 = (s.w < 0) ? bp : __ldg(&x4[(size_t)s.w * 32 + dg]);
        pxv = __ldg(&x4[(size_t)i * 32 + dg]);
    }

#pragma unroll
    for (int it = 0; it < NIT; it++) {
        float4 nv0, nv1, nv2, nv3, nxv;
        int nvalid = 0, nloc = 0;
        if (it + 1 < NIT) {                    // compile-time after unroll
            int local = (it + 1) * 8 + sub;
            nloc   = local;
            nvalid = (local < NPB) && (blockStart + local < NN);
            int li = (local < NPB) ? local : NPB - 1;
            int i = blockStart + li; if (i >= NN) i = NN - 1;
            int4 s = s_srcn[li];
            nv0 = (s.x < 0) ? bp : __ldg(&x4[(size_t)s.x * 32 + dg]);
            nv1 = (s.y < 0) ? bp : __ldg(&x4[(size_t)s.y * 32 + dg]);
            nv2 = (s.z < 0) ? bp : __ldg(&x4[(size_t)s.z * 32 + dg]);
            nv3 = (s.w < 0) ? bp : __ldg(&x4[(size_t)s.w * 32 + dg]);
            nxv = __ldg(&x4[(size_t)i * 32 + dg]);
        }

        if (pvalid) {
            float4 v0 = pv0, v1 = pv1, v2 = pv2, v3 = pv3;
            float t;
#define CSWAP(A,B) \
            t = fminf(A.x,B.x); B.x = fmaxf(A.x,B.x); A.x = t; \
            t = fminf(A.y,B.y); B.y = fmaxf(A.y,B.y); A.y = t; \
            t = fminf(A.z,B.z); B.z = fmaxf(A.z,B.z); A.z = t; \
            t = fminf(A.w,B.w); B.w = fmaxf(A.w,B.w); A.w = t;
            CSWAP(v0, v1)
            CSWAP(v2, v3)
            CSWAP(v0, v2)
            CSWAP(v1, v3)
            CSWAP(v1, v2)
#undef CSWAP
            float4 hv;
            hv.x = av * pxv.x + v0.x * c0 + v1.x * c1 + v2.x * c2 + v3.x * c3 + cbv;
            hv.y = av * pxv.y + v0.y * c0 + v1.y * c1 + v2.y * c2 + v3.y * c3 + cbv;
            hv.z = av * pxv.z + v0.z * c0 + v1.z * c1 + v2.z * c2 + v3.z * c3 + cbv;
            hv.w = av * pxv.w + v0.w * c0 + v1.w * c1 + v2.w * c2 + v3.w * c3 + cbv;
            sh[ploc * 32 + dg] = hv;
            lsum.x += hv.x; lsum.y += hv.y; lsum.z += hv.z; lsum.w += hv.w;
            lsq.x += hv.x * hv.x; lsq.y += hv.y * hv.y;
            lsq.z += hv.z * hv.z; lsq.w += hv.w * hv.w;
        }

        pv0 = nv0; pv1 = nv1; pv2 = nv2; pv3 = nv3; pxv = nxv;
        pvalid = nvalid; ploc = nloc;
    }

    // ---- block reduce + global partials ----
    ssum[threadIdx.x] = lsum;
    ssq[threadIdx.x]  = lsq;
    __syncthreads();
    if (threadIdx.x < 32) {
        float4 a = ssum[threadIdx.x];
        float4 q = ssq[threadIdx.x];
#pragma unroll
        for (int k = 1; k < 8; k++) {
            float4 a2 = ssum[threadIdx.x + 32 * k];
            float4 q2 = ssq[threadIdx.x + 32 * k];
            a.x += a2.x; a.y += a2.y; a.z += a2.z; a.w += a2.w;
            q.x += q2.x; q.y += q2.y; q.z += q2.z; q.w += q2.w;
        }
        int d0 = threadIdx.x * 4;
        atomicAdd(&g_sum[layer][d0 + 0], a.x);
        atomicAdd(&g_sum[layer][d0 + 1], a.y);
        atomicAdd(&g_sum[layer][d0 + 2], a.z);
        atomicAdd(&g_sum[layer][d0 + 3], a.w);
        atomicAdd(&g_sq[layer][d0 + 0], q.x);
        atomicAdd(&g_sq[layer][d0 + 1], q.y);
        atomicAdd(&g_sq[layer][d0 + 2], q.z);
        atomicAdd(&g_sq[layer][d0 + 3], q.w);
    }

    // ---- soft grid barrier (all blocks co-resident) ----
    __threadfence();
    if (threadIdx.x == 0) {
        atomicAdd(&g_done[layer], 1);
        volatile int* dp = &g_done[layer];
        while (*dp < NBLOCKS) { __nanosleep(100); }
    }
    __syncthreads();
    __threadfence();

    // ---- phase 2: stats + apply ----
    if (threadIdx.x < DD) {
        int d = threadIdx.x;
        float mu  = __ldcg(&g_sum[layer][d]) * (1.0f / NN);
        float var = __ldcg(&g_sq[layer][d]) * (1.0f / NN) - mu * mu;
        smu[d]    = mu;
        sscale[d] = rsqrtf(var + 1e-5f) * __ldg(&gamma[d]);
    }
    __syncthreads();

    int d0 = dg * 4;
    float m0 = smu[d0], m1 = smu[d0 + 1], m2 = smu[d0 + 2], m3 = smu[d0 + 3];
    float s0 = sscale[d0], s1 = sscale[d0 + 1], s2 = sscale[d0 + 2], s3 = sscale[d0 + 3];
    float e0 = __ldg(&beta[d0]), e1 = __ldg(&beta[d0 + 1]);
    float e2 = __ldg(&beta[d0 + 2]), e3 = __ldg(&beta[d0 + 3]);

#pragma unroll 4
    for (int it = 0; it < NIT; it++) {
        int local = it * 8 + sub;
        int i = blockStart + local;
        if (local < NPB && i < NN) {
            float4 hv = sh[local * 32 + dg];
            float4 xv = __ldg(&x4[(size_t)i * 32 + dg]);
            float4 o;
            o.x = xv.x + (hv.x - m0) * s0 + e0;
            o.y = xv.y + (hv.y - m1) * s1 + e1;
            o.z = xv.z + (hv.z - m2) * s2 + e2;
            o.w = xv.w + (hv.w - m3) * s3 + e3;
            out4[(size_t)i * 32 + dg] = o;
        }
    }
}

// ---------------- launch -----------------------------------------------------

extern "C" void kernel_launch(void* const* d_in, const int* in_sizes, int n_in,
                              void* d_out, int out_size)
{
    const float* x   = (const float*)d_in[0];
    const int*   ei  = (const int*)d_in[1];
    const int*   src = ei;        // edge_index[0]
    const int*   dst = ei + EE;   // edge_index[1]

    const float* W0     = (const float*)d_in[2];
    const float* b0     = (const float*)d_in[3];
    const float* cw0    = (const float*)d_in[4];
    const float* cb0    = (const float*)d_in[5];
    const float* a0     = (const float*)d_in[6];
    const float* g0     = (const float*)d_in[7];
    const float* be0    = (const float*)d_in[8];
    const float* blank0 = (const float*)d_in[9];
    const float* W1     = (const float*)d_in[10];
    const float* b1     = (const float*)d_in[11];
    const float* cw1    = (const float*)d_in[12];
    const float* cb1    = (const float*)d_in[13];
    const float* a1     = (const float*)d_in[14];
    const float* g1     = (const float*)d_in[15];
    const float* be1    = (const float*)d_in[16];
    const float* blank1 = (const float*)d_in[17];

    float* out = (float*)d_out;

    const int smem_bytes = NPB * 32 * sizeof(float4);   // 57,856 B

    static bool attr_set = false;
    if (!attr_set) {
        cudaFuncSetAttribute(fused_kernel,
                             cudaFuncAttributeMaxDynamicSharedMemorySize, smem_bytes);
        attr_set = true;
    }

    // slots init: 0xFF byte pattern == SLOT_INF (unsigned), via async memset
    void* slots_ptr = nullptr;
    cudaGetSymbolAddress(&slots_ptr, g_slots);
    cudaMemsetAsync(slots_ptr, 0xFF, sizeof(unsigned) * NN * MAXN);

    // edge pass (1 edge/thread) + (extra block) blankp/stat-zero
    edge_pass_kernel<<<EDGE_BLOCKS + 1, 256>>>(dst,
                                               W0, b0, blank0, W1, b1, blank1);

    // layer 0: reads x, writes x1 into d_out
    fused_kernel<<<NBLOCKS, 256, smem_bytes>>>((const float4*)x, src, cw0, cb0, a0,
                                               g0, be0, (float4*)out, 0);
    // layer 1: reads d_out, writes final into d_out (safe: all gathers precede
    // any write because every write is after the grid barrier)
    fused_kernel<<<NBLOCKS, 256, smem_bytes>>>((const float4*)out, src, cw1, cb1, a1,
                                               g1, be1, (float4*)out, 1);
}

// round 15
// speedup vs baseline: 1.0324x; 1.0078x over previous
#include <cuda_runtime.h>
#include <cuda_bf16.h>
#include <math.h>

#define NN 50000
#define EE 800000
#define DD 128
#define MAXN 4
#define SLOT_INF 0xFFFFFFFFu
#define NBLOCKS 444            // 148 SMs x 3 resident blocks (co-resident by construction)
#define NPB 113                // ceil(50000/444) nodes per block
#define NIT 15                 // ceil(113/8) iterations per sub-lane
#define EDGE_BLOCKS ((EE / 4 + 255) / 256)

// ---------------- scratch (device globals; no allocation allowed) ----------
__device__ unsigned g_slots[NN * MAXN];    // 4 smallest in-edge ids per node
__device__ float    g_blankp[2][DD];
__device__ float    g_sum[2][DD];
__device__ float    g_sq[2][DD];
__device__ int      g_done[2];

// ---------------- kernels ---------------------------------------------------

// Insert v into the sorted top-4 slot line starting at slot p (all slots k<p
// provably fail their atomicMin — see caller).
__device__ __forceinline__ void slot_insert_from(unsigned* sl, unsigned v, int p) {
    for (int k = p; k < MAXN; k++) {
        unsigned old = atomicMin(&sl[k], v);
        if (old == SLOT_INF) break;   // inserted into empty slot
        v = max(v, old);              // displaced (larger) value cascades
    }
}

// Edge pass, prefix-skip cascade. For each edge: one 16B plain (L1) read of
// the slot line. Stale values are stale-HIGH only (slots monotonically
// decrease; atomics bypass L1), so stale s[k] <= v implies true[k] <= v,
// implying atomicMin(sl[k], v) would fail and leave v unchanged. Skipping
// that PREFIX is therefore exactly equivalent to executing it. The cascade
// starts at the first k with v < s[k]; if none, the edge is pruned outright.
// This cuts the serial per-hot-node atomic chain (the kernel's binding
// constraint) by ~2x.
// One extra block computes blank_p for both layers + zeroes stats/barriers.
__global__ void edge_pass_kernel(const int4* __restrict__ dst4,
                                 const float* __restrict__ W0, const float* __restrict__ b0,
                                 const float* __restrict__ blank0,
                                 const float* __restrict__ W1, const float* __restrict__ b1,
                                 const float* __restrict__ blank1)
{
    if ((int)blockIdx.x < EDGE_BLOCKS) {
        int t = blockIdx.x * blockDim.x + threadIdx.x;
        if (t >= EE / 4) return;
        int4 d = __ldg(&dst4[t]);
        unsigned e0 = (unsigned)(t * 4);
#pragma unroll
        for (int j = 0; j < 4; j++) {
            int node = (j == 0) ? d.x : (j == 1) ? d.y : (j == 2) ? d.z : d.w;
            unsigned v = e0 + (unsigned)j;
            unsigned* sl = &g_slots[node * MAXN];
            uint4 s = *reinterpret_cast<const uint4*>(sl);   // plain L1 read, stale-high
            int p;
            if      (v < s.x) p = 0;
            else if (v < s.y) p = 1;
            else if (v < s.z) p = 2;
            else if (v < s.w) p = 3;
            else continue;                                    // pruned: fails everywhere
            slot_insert_from(sl, v, p);
        }
    } else {
        // blankp for both layers + zero stats + barrier counters
        int t = threadIdx.x;           // 0..255
        int layer = t >> 7;            // 0 or 1
        int d = t & 127;
        const float* W  = layer ? W1 : W0;
        const float* b  = layer ? b1 : b0;
        const float* bl = layer ? blank1 : blank0;
        float s = b[d];
#pragma unroll 8
        for (int j = 0; j < DD; j++) s += W[d * DD + j] * bl[j];
        g_blankp[layer][d] = s;
        g_sum[layer][d] = 0.0f;
        g_sq[layer][d]  = 0.0f;
        if (t == 0) { g_done[0] = 0; g_done[1] = 0; }
    }
}

// Fused persistent conv + batchnorm-apply, software-pipelined phase 1.
// Phase 0 converts this block's slot records (edge ids) into source-node ids
// directly in smem — no global srcn array, no prep kernel.
__global__ __launch_bounds__(256, 3) void fused_kernel(
    const float4* __restrict__ x4, const int* __restrict__ src,
    const float* __restrict__ cw, const float* __restrict__ cb,
    const float* __restrict__ a_p,
    const float* __restrict__ gamma, const float* __restrict__ beta,
    float4* __restrict__ out4, int layer)
{
    extern __shared__ float4 sh[];          // [NPB][32] h rows
    __shared__ int4   s_srcn[NPB];
    __shared__ float4 ssum[256];
    __shared__ float4 ssq[256];
    __shared__ float  smu[DD];
    __shared__ float  sscale[DD];

    int dg  = threadIdx.x & 31;    // dim group: dims 4*dg .. 4*dg+3
    int sub = threadIdx.x >> 5;    // 0..7 node sub-lanes
    float c0 = __ldg(cw + 0), c1 = __ldg(cw + 1), c2 = __ldg(cw + 2), c3 = __ldg(cw + 3);
    float cbv = __ldg(cb);
    float av  = __ldg(a_p);
    float4 bp = *reinterpret_cast<const float4*>(&g_blankp[layer][dg * 4]);

    int blockStart = blockIdx.x * NPB;

    // ---- phase 0: slots -> srcn window, straight into smem ----
    for (int k = threadIdx.x; k < NPB; k += 256) {
        int i = blockStart + k;
        int4 r = make_int4(-1, -1, -1, -1);
        if (i < NN) {
            uint4 s = *reinterpret_cast<const uint4*>(&g_slots[i * 4]);
            r.x = (s.x == SLOT_INF) ? -1 : __ldg(&src[s.x]);
            r.y = (s.y == SLOT_INF) ? -1 : __ldg(&src[s.y]);
            r.z = (s.z == SLOT_INF) ? -1 : __ldg(&src[s.z]);
            r.w = (s.w == SLOT_INF) ? -1 : __ldg(&src[s.w]);
        }
        s_srcn[k] = r;
    }
    __syncthreads();

    float4 lsum = make_float4(0.f, 0.f, 0.f, 0.f);
    float4 lsq  = make_float4(0.f, 0.f, 0.f, 0.f);

    // ---- phase 1: conv into smem, 2-stage software pipeline ----
    float4 pv0, pv1, pv2, pv3, pxv;
    int pvalid, ploc;
    {
        int local = sub;                       // it = 0; sub < 8 <= NPB
        ploc   = local;
        pvalid = (blockStart + local < NN);
        int i = blockStart + local; if (i >= NN) i = NN - 1;
        int4 s = s_srcn[local];
        pv0 = (s.x < 0) ? bp : __ldg(&x4[(size_t)s.x * 32 + dg]);
        pv1 = (s.y < 0) ? bp : __ldg(&x4[(size_t)s.y * 32 + dg]);
        pv2 = (s.z < 0) ? bp : __ldg(&x4[(size_t)s.z * 32 + dg]);
        pv3 = (s.w < 0) ? bp : __ldg(&x4[(size_t)s.w * 32 + dg]);
        pxv = __ldg(&x4[(size_t)i * 32 + dg]);
    }

#pragma unroll
    for (int it = 0; it < NIT; it++) {
        float4 nv0, nv1, nv2, nv3, nxv;
        int nvalid = 0, nloc = 0;
        if (it + 1 < NIT) {                    // compile-time after unroll
            int local = (it + 1) * 8 + sub;
            nloc   = local;
            nvalid = (local < NPB) && (blockStart + local < NN);
            int li = (local < NPB) ? local : NPB - 1;
            int i = blockStart + li; if (i >= NN) i = NN - 1;
            int4 s = s_srcn[li];
            nv0 = (s.x < 0) ? bp : __ldg(&x4[(size_t)s.x * 32 + dg]);
            nv1 = (s.y < 0) ? bp : __ldg(&x4[(size_t)s.y * 32 + dg]);
            nv2 = (s.z < 0) ? bp : __ldg(&x4[(size_t)s.z * 32 + dg]);
            nv3 = (s.w < 0) ? bp : __ldg(&x4[(size_t)s.w * 32 + dg]);
            nxv = __ldg(&x4[(size_t)i * 32 + dg]);
        }

        if (pvalid) {
            float4 v0 = pv0, v1 = pv1, v2 = pv2, v3 = pv3;
            float t;
#define CSWAP(A,B) \
            t = fminf(A.x,B.x); B.x = fmaxf(A.x,B.x); A.x = t; \
            t = fminf(A.y,B.y); B.y = fmaxf(A.y,B.y); A.y = t; \
            t = fminf(A.z,B.z); B.z = fmaxf(A.z,B.z); A.z = t; \
            t = fminf(A.w,B.w); B.w = fmaxf(A.w,B.w); A.w = t;
            CSWAP(v0, v1)
            CSWAP(v2, v3)
            CSWAP(v0, v2)
            CSWAP(v1, v3)
            CSWAP(v1, v2)
#undef CSWAP
            float4 hv;
            hv.x = av * pxv.x + v0.x * c0 + v1.x * c1 + v2.x * c2 + v3.x * c3 + cbv;
            hv.y = av * pxv.y + v0.y * c0 + v1.y * c1 + v2.y * c2 + v3.y * c3 + cbv;
            hv.z = av * pxv.z + v0.z * c0 + v1.z * c1 + v2.z * c2 + v3.z * c3 + cbv;
            hv.w = av * pxv.w + v0.w * c0 + v1.w * c1 + v2.w * c2 + v3.w * c3 + cbv;
            sh[ploc * 32 + dg] = hv;
            lsum.x += hv.x; lsum.y += hv.y; lsum.z += hv.z; lsum.w += hv.w;
            lsq.x += hv.x * hv.x; lsq.y += hv.y * hv.y;
            lsq.z += hv.z * hv.z; lsq.w += hv.w * hv.w;
        }

        pv0 = nv0; pv1 = nv1; pv2 = nv2; pv3 = nv3; pxv = nxv;
        pvalid = nvalid; ploc = nloc;
    }

    // ---- block reduce + global partials ----
    ssum[threadIdx.x] = lsum;
    ssq[threadIdx.x]  = lsq;
    __syncthreads();
    if (threadIdx.x < 32) {
        float4 a = ssum[threadIdx.x];
        float4 q = ssq[threadIdx.x];
#pragma unroll
        for (int k = 1; k < 8; k++) {
            float4 a2 = ssum[threadIdx.x + 32 * k];
            float4 q2 = ssq[threadIdx.x + 32 * k];
            a.x += a2.x; a.y += a2.y; a.z += a2.z; a.w += a2.w;
            q.x += q2.x; q.y += q2.y; q.z += q2.z; q.w += q2.w;
        }
        int d0 = threadIdx.x * 4;
        atomicAdd(&g_sum[layer][d0 + 0], a.x);
        atomicAdd(&g_sum[layer][d0 + 1], a.y);
        atomicAdd(&g_sum[layer][d0 + 2], a.z);
        atomicAdd(&g_sum[layer][d0 + 3], a.w);
        atomicAdd(&g_sq[layer][d0 + 0], q.x);
        atomicAdd(&g_sq[layer][d0 + 1], q.y);
        atomicAdd(&g_sq[layer][d0 + 2], q.z);
        atomicAdd(&g_sq[layer][d0 + 3], q.w);
    }

    // ---- soft grid barrier (all blocks co-resident) ----
    __threadfence();
    if (threadIdx.x == 0) {
        atomicAdd(&g_done[layer], 1);
        volatile int* dp = &g_done[layer];
        while (*dp < NBLOCKS) { __nanosleep(100); }
    }
    __syncthreads();
    __threadfence();

    // ---- phase 2: stats + apply ----
    if (threadIdx.x < DD) {
        int d = threadIdx.x;
        float mu  = __ldcg(&g_sum[layer][d]) * (1.0f / NN);
        float var = __ldcg(&g_sq[layer][d]) * (1.0f / NN) - mu * mu;
        smu[d]    = mu;
        sscale[d] = rsqrtf(var + 1e-5f) * __ldg(&gamma[d]);
    }
    __syncthreads();

    int d0 = dg * 4;
    float m0 = smu[d0], m1 = smu[d0 + 1], m2 = smu[d0 + 2], m3 = smu[d0 + 3];
    float s0 = sscale[d0], s1 = sscale[d0 + 1], s2 = sscale[d0 + 2], s3 = sscale[d0 + 3];
    float e0 = __ldg(&beta[d0]), e1 = __ldg(&beta[d0 + 1]);
    float e2 = __ldg(&beta[d0 + 2]), e3 = __ldg(&beta[d0 + 3]);

#pragma unroll 4
    for (int it = 0; it < NIT; it++) {
        int local = it * 8 + sub;
        int i = blockStart + local;
        if (local < NPB && i < NN) {
            float4 hv = sh[local * 32 + dg];
            float4 xv = __ldg(&x4[(size_t)i * 32 + dg]);
            float4 o;
            o.x = xv.x + (hv.x - m0) * s0 + e0;
            o.y = xv.y + (hv.y - m1) * s1 + e1;
            o.z = xv.z + (hv.z - m2) * s2 + e2;
            o.w = xv.w + (hv.w - m3) * s3 + e3;
            out4[(size_t)i * 32 + dg] = o;
        }
    }
}

// ---------------- launch -----------------------------------------------------

extern "C" void kernel_launch(void* const* d_in, const int* in_sizes, int n_in,
                              void* d_out, int out_size)
{
    const float* x   = (const float*)d_in[0];
    const int*   ei  = (const int*)d_in[1];
    const int*   src = ei;        // edge_index[0]
    const int*   dst = ei + EE;   // edge_index[1]

    const float* W0     = (const float*)d_in[2];
    const float* b0     = (const float*)d_in[3];
    const float* cw0    = (const float*)d_in[4];
    const float* cb0    = (const float*)d_in[5];
    const float* a0     = (const float*)d_in[6];
    const float* g0     = (const float*)d_in[7];
    const float* be0    = (const float*)d_in[8];
    const float* blank0 = (const float*)d_in[9];
    const float* W1     = (const float*)d_in[10];
    const float* b1     = (const float*)d_in[11];
    const float* cw1    = (const float*)d_in[12];
    const float* cb1    = (const float*)d_in[13];
    const float* a1     = (const float*)d_in[14];
    const float* g1     = (const float*)d_in[15];
    const float* be1    = (const float*)d_in[16];
    const float* blank1 = (const float*)d_in[17];

    float* out = (float*)d_out;

    const int smem_bytes = NPB * 32 * sizeof(float4);   // 57,856 B

    static bool attr_set = false;
    if (!attr_set) {
        cudaFuncSetAttribute(fused_kernel,
                             cudaFuncAttributeMaxDynamicSharedMemorySize, smem_bytes);
        attr_set = true;
    }

    // slots init: 0xFF byte pattern == SLOT_INF (unsigned), via async memset
    void* slots_ptr = nullptr;
    cudaGetSymbolAddress(&slots_ptr, g_slots);
    cudaMemsetAsync(slots_ptr, 0xFF, sizeof(unsigned) * NN * MAXN);

    // edge pass + (extra block) blankp/stat-zero
    edge_pass_kernel<<<EDGE_BLOCKS + 1, 256>>>((const int4*)dst,
                                               W0, b0, blank0, W1, b1, blank1);

    // layer 0: reads x, writes x1 into d_out
    fused_kernel<<<NBLOCKS, 256, smem_bytes>>>((const float4*)x, src, cw0, cb0, a0,
                                               g0, be0, (float4*)out, 0);
    // layer 1: reads d_out, writes final into d_out (safe: all gathers precede
    // any write because every write is after the grid barrier)
    fused_kernel<<<NBLOCKS, 256, smem_bytes>>>((const float4*)out, src, cw1, cb1, a1,
                                               g1, be1, (float4*)out, 1);
}